// round 1
// baseline (speedup 1.0000x reference)
#include <cuda_runtime.h>
#include <cuda_bf16.h>
#include <math.h>

// Problem constants (shapes are fixed by the dataset)
#define B_DIM   2
#define N_DIM   2048
#define C_DIM   1024
#define NH      16
#define HD      64
#define M_ROWS  (B_DIM * N_DIM)          // 4096
#define QKV_N   (3 * C_DIM)              // 3072

// Scratch (allocation-free rule: __device__ globals)
__device__ float g_qkv[(size_t)M_ROWS * QKV_N];   // [4096][3072]
__device__ float g_attn[(size_t)M_ROWS * C_DIM];  // [4096][1024]

// ---------------------------------------------------------------------------
// SGEMM NT: C[m][n] = sum_c A[m][c] * W[n][c] (+bias[n])
// A row-major [M,K], W row-major [N,K]. 128x128x16 tile, 256 thr, 8x8/thread.
// ---------------------------------------------------------------------------
template<bool BIAS>
__global__ void __launch_bounds__(256) sgemm_nt(
    const float* __restrict__ A, const float* __restrict__ Wm,
    const float* __restrict__ bias, float* __restrict__ C,
    int M, int N, int K)
{
    __shared__ float As[16][132];
    __shared__ float Bs[16][132];

    const int tid  = threadIdx.x;
    const int row0 = blockIdx.y * 128;
    const int col0 = blockIdx.x * 128;
    const int lr = tid >> 2;            // 0..63
    const int lc = (tid & 3) << 2;      // 0,4,8,12
    const int tx = tid & 15, ty = tid >> 4;

    const float* Ap  = A  + (size_t)(row0 + lr) * K + lc;
    const float* Ap2 = Ap + (size_t)64 * K;
    const float* Wp  = Wm + (size_t)(col0 + lr) * K + lc;
    const float* Wp2 = Wp + (size_t)64 * K;

    float acc[8][8];
    #pragma unroll
    for (int i = 0; i < 8; i++)
        #pragma unroll
        for (int j = 0; j < 8; j++) acc[i][j] = 0.f;

    for (int k0 = 0; k0 < K; k0 += 16) {
        float4 a0 = *(const float4*)(Ap  + k0);
        float4 a1 = *(const float4*)(Ap2 + k0);
        float4 b0 = *(const float4*)(Wp  + k0);
        float4 b1 = *(const float4*)(Wp2 + k0);
        __syncthreads();
        As[lc+0][lr] = a0.x; As[lc+1][lr] = a0.y; As[lc+2][lr] = a0.z; As[lc+3][lr] = a0.w;
        As[lc+0][lr+64] = a1.x; As[lc+1][lr+64] = a1.y; As[lc+2][lr+64] = a1.z; As[lc+3][lr+64] = a1.w;
        Bs[lc+0][lr] = b0.x; Bs[lc+1][lr] = b0.y; Bs[lc+2][lr] = b0.z; Bs[lc+3][lr] = b0.w;
        Bs[lc+0][lr+64] = b1.x; Bs[lc+1][lr+64] = b1.y; Bs[lc+2][lr+64] = b1.z; Bs[lc+3][lr+64] = b1.w;
        __syncthreads();

        #pragma unroll
        for (int kk = 0; kk < 16; kk++) {
            float ra[8], rb[8];
            *(float4*)&ra[0] = *(const float4*)&As[kk][ty*8];
            *(float4*)&ra[4] = *(const float4*)&As[kk][ty*8+4];
            *(float4*)&rb[0] = *(const float4*)&Bs[kk][tx*8];
            *(float4*)&rb[4] = *(const float4*)&Bs[kk][tx*8+4];
            #pragma unroll
            for (int i = 0; i < 8; i++)
                #pragma unroll
                for (int j = 0; j < 8; j++)
                    acc[i][j] += ra[i] * rb[j];
        }
    }

    #pragma unroll
    for (int i = 0; i < 8; i++) {
        int r = row0 + ty*8 + i;
        float* crow = C + (size_t)r * N + col0 + tx*8;
        #pragma unroll
        for (int j = 0; j < 8; j += 4) {
            float4 v;
            v.x = acc[i][j+0]; v.y = acc[i][j+1]; v.z = acc[i][j+2]; v.w = acc[i][j+3];
            if (BIAS) {
                const float* bp = bias + col0 + tx*8 + j;
                v.x += bp[0]; v.y += bp[1]; v.z += bp[2]; v.w += bp[3];
            }
            *(float4*)(crow + j) = v;
        }
    }
}

// ---------------------------------------------------------------------------
// Axial RoPE, in-place on q and k inside the qkv buffer.
// Torch .repeat tiling: element j in a 20-dim segment uses omega[j % 10],
// rotation partner is the adjacent element within the (2i, 2i+1) pair.
// ---------------------------------------------------------------------------
#define ROPE_TOTAL (2 * B_DIM * NH * N_DIM * 30)   // {q,k} x b x h x n x 30 pairs

__global__ void rope_kernel(float* __restrict__ qkv)
{
    int idx = blockIdx.x * blockDim.x + threadIdx.x;
    if (idx >= ROPE_TOTAL) return;
    int pair = idx % 30; int t = idx / 30;
    int n = t & 2047; t >>= 11;
    int h = t & 15;   t >>= 4;
    int b = t & 1;    int sel = t >> 1;   // 0 = q, 1 = k

    int seg = pair / 10;
    int ip  = pair - seg * 10;

    float p;
    if (seg == 0)      p = (float)(n >> 8);          // d_pos = n / 256
    else if (seg == 1) p = (float)((n >> 4) & 15);   // h_pos = (n%256)/16 * 1.0
    else               p = (float)(n & 15);          // w_pos = (n%16) * 1.0

    int j0 = 2 * ip, j1 = 2 * ip + 1;
    int f0 = (j0 < 10) ? j0 : j0 - 10;
    int f1 = (j1 < 10) ? j1 : j1 - 10;
    float om0 = __powf(10000.f, -0.1f * (float)f0);
    float om1 = __powf(10000.f, -0.1f * (float)f1);

    size_t base = ((size_t)(b * N_DIM + n)) * QKV_N + sel * C_DIM + h * HD + seg * 20;
    float x0 = qkv[base + j0];
    float x1 = qkv[base + j1];

    float sn0, cs0, sn1, cs1;
    sincosf(p * om0, &sn0, &cs0);
    sincosf(p * om1, &sn1, &cs1);

    qkv[base + j0] = x0 * cs0 - x1 * sn0;   // x0*cos + (-x1)*sin
    qkv[base + j1] = x1 * cs1 + x0 * sn1;   // x1*cos + ( x0)*sin
}

// ---------------------------------------------------------------------------
// Flash attention. CTA = 64 q-rows for one (b,h). 8 warps, warp owns 8 rows.
// Lane owns columns {lane, lane+32}. Transposed smem tiles make the S and PV
// inner loops 2x LDS.128 (broadcast) + 2x LDS.32 per 16 FMAs.
// ---------------------------------------------------------------------------
#define QT_LD 68
#define KT_LD 65
#define VS_LD 65
#define PT_LD 68
#define ATTN_SMEM ((64*QT_LD + 64*KT_LD + 64*VS_LD + 64*PT_LD) * 4)

__global__ void __launch_bounds__(256) attn_kernel(
    const float* __restrict__ qkv, float* __restrict__ out)
{
    extern __shared__ float sm[];
    float* Qt = sm;                       // [64][68]  Qt[k][r], pre-scaled
    float* Kt = Qt + 64*QT_LD;            // [64][65]  Kt[k][j]
    float* Vs = Kt + 64*KT_LD;            // [64][65]  Vs[j][c]
    float* Pt = Vs + 64*VS_LD;            // [64][68]  Pt[j][r]

    const int tid  = threadIdx.x;
    const int lane = tid & 31;
    const int w    = tid >> 5;            // warp 0..7
    const int bh = blockIdx.y;
    const int b = bh >> 4, h = bh & 15;
    const int n0 = blockIdx.x * 64;
    const float scale = 0.125f;           // hd^-0.5

    // Load Q tile transposed (scaled). thread: row r = tid/4, k-base (tid%4)*16
    {
        int r  = tid >> 2;
        int kb = (tid & 3) << 4;
        const float* src = qkv + ((size_t)(b * N_DIM + n0 + r)) * QKV_N + h * HD + kb;
        #pragma unroll
        for (int i = 0; i < 4; i++) {
            float4 v = *(const float4*)(src + i*4);
            int k = kb + i*4;
            Qt[(k+0)*QT_LD + r] = v.x * scale;
            Qt[(k+1)*QT_LD + r] = v.y * scale;
            Qt[(k+2)*QT_LD + r] = v.z * scale;
            Qt[(k+3)*QT_LD + r] = v.w * scale;
        }
    }

    float m_i[8], l_i[8], o0[8], o1[8];
    #pragma unroll
    for (int r = 0; r < 8; r++) { m_i[r] = -1e30f; l_i[r] = 0.f; o0[r] = 0.f; o1[r] = 0.f; }

    for (int kt = 0; kt < N_DIM / 64; kt++) {
        const int kn0 = kt * 64;
        __syncthreads();
        // Load K (transposed) and V (direct) tiles
        {
            int j  = tid >> 2;
            int kb = (tid & 3) << 4;
            const float* ksrc = qkv + ((size_t)(b * N_DIM + kn0 + j)) * QKV_N + C_DIM   + h * HD + kb;
            const float* vsrc = qkv + ((size_t)(b * N_DIM + kn0 + j)) * QKV_N + 2*C_DIM + h * HD + kb;
            #pragma unroll
            for (int i = 0; i < 4; i++) {
                float4 kv = *(const float4*)(ksrc + i*4);
                int k = kb + i*4;
                Kt[(k+0)*KT_LD + j] = kv.x;
                Kt[(k+1)*KT_LD + j] = kv.y;
                Kt[(k+2)*KT_LD + j] = kv.z;
                Kt[(k+3)*KT_LD + j] = kv.w;
                float4 vv = *(const float4*)(vsrc + i*4);
                Vs[j*VS_LD + k+0] = vv.x;
                Vs[j*VS_LD + k+1] = vv.y;
                Vs[j*VS_LD + k+2] = vv.z;
                Vs[j*VS_LD + k+3] = vv.w;
            }
        }
        __syncthreads();

        // S = Q K^T   (lane: cols lane, lane+32; rows w*8..w*8+7)
        float s0[8], s1[8];
        #pragma unroll
        for (int r = 0; r < 8; r++) { s0[r] = 0.f; s1[r] = 0.f; }
        #pragma unroll 8
        for (int k = 0; k < 64; k++) {
            float q[8];
            *(float4*)&q[0] = *(const float4*)&Qt[k*QT_LD + w*8];
            *(float4*)&q[4] = *(const float4*)&Qt[k*QT_LD + w*8 + 4];
            float kv0 = Kt[k*KT_LD + lane];
            float kv1 = Kt[k*KT_LD + lane + 32];
            #pragma unroll
            for (int r = 0; r < 8; r++) {
                s0[r] += q[r] * kv0;
                s1[r] += q[r] * kv1;
            }
        }

        // Online softmax per row (warp-wide)
        #pragma unroll
        for (int r = 0; r < 8; r++) {
            float tmax = fmaxf(s0[r], s1[r]);
            #pragma unroll
            for (int off = 16; off; off >>= 1)
                tmax = fmaxf(tmax, __shfl_xor_sync(0xffffffffu, tmax, off));
            float mn = fmaxf(m_i[r], tmax);
            float alpha = __expf(m_i[r] - mn);
            float p0 = __expf(s0[r] - mn);
            float p1 = __expf(s1[r] - mn);
            float rs = p0 + p1;
            #pragma unroll
            for (int off = 16; off; off >>= 1)
                rs += __shfl_xor_sync(0xffffffffu, rs, off);
            l_i[r] = l_i[r] * alpha + rs;
            m_i[r] = mn;
            o0[r] *= alpha;
            o1[r] *= alpha;
            Pt[lane*PT_LD + w*8 + r]      = p0;
            Pt[(lane+32)*PT_LD + w*8 + r] = p1;
        }
        __syncwarp();

        // O += P @ V
        #pragma unroll 8
        for (int j = 0; j < 64; j++) {
            float pr[8];
            *(float4*)&pr[0] = *(const float4*)&Pt[j*PT_LD + w*8];
            *(float4*)&pr[4] = *(const float4*)&Pt[j*PT_LD + w*8 + 4];
            float v0 = Vs[j*VS_LD + lane];
            float v1 = Vs[j*VS_LD + lane + 32];
            #pragma unroll
            for (int r = 0; r < 8; r++) {
                o0[r] += pr[r] * v0;
                o1[r] += pr[r] * v1;
            }
        }
    }

    // Normalize and write out[b][n][h*64 + c]
    #pragma unroll
    for (int r = 0; r < 8; r++) {
        float inv = 1.0f / l_i[r];
        size_t orow = ((size_t)(b * N_DIM + n0 + w*8 + r)) * C_DIM + h * HD;
        out[orow + lane]      = o0[r] * inv;
        out[orow + lane + 32] = o1[r] * inv;
    }
}

// ---------------------------------------------------------------------------
extern "C" void kernel_launch(void* const* d_in, const int* in_sizes, int n_in,
                              void* d_out, int out_size)
{
    const float* x     = (const float*)d_in[0];
    const float* Wqkv  = (const float*)d_in[1];
    const float* Wproj = (const float*)d_in[2];
    const float* bproj = (const float*)d_in[3];
    // d_in[4..6] = T,H,W scalars; shapes are fixed, hardcoded above.
    float* out = (float*)d_out;

    float *qkv_ptr, *attn_ptr;
    cudaGetSymbolAddress((void**)&qkv_ptr,  g_qkv);
    cudaGetSymbolAddress((void**)&attn_ptr, g_attn);

    cudaFuncSetAttribute(attn_kernel,
                         cudaFuncAttributeMaxDynamicSharedMemorySize, ATTN_SMEM);

    // 1) fused QKV projection: [4096,1024] x [3072,1024]^T -> [4096,3072]
    sgemm_nt<false><<<dim3(QKV_N/128, M_ROWS/128), 256>>>(
        x, Wqkv, nullptr, qkv_ptr, M_ROWS, QKV_N, C_DIM);

    // 2) axial RoPE on q,k (in place)
    rope_kernel<<<(ROPE_TOTAL + 255) / 256, 256>>>(qkv_ptr);

    // 3) SDPA -> [4096,1024] (already in (b,n,h*hd) layout)
    attn_kernel<<<dim3(N_DIM/64, B_DIM*NH), 256, ATTN_SMEM>>>(qkv_ptr, attn_ptr);

    // 4) output projection + bias
    sgemm_nt<true><<<dim3(C_DIM/128, M_ROWS/128), 256>>>(
        attn_ptr, Wproj, bproj, out, M_ROWS, C_DIM, C_DIM);
}

// round 3
// speedup vs baseline: 2.5162x; 2.5162x over previous
#include <cuda_runtime.h>
#include <math.h>
#include <stdint.h>

#define B_DIM   2
#define N_DIM   2048
#define C_DIM   1024
#define NH      16
#define HD      64
#define M_ROWS  (B_DIM * N_DIM)          // 4096
#define QKV_N   (3 * C_DIM)              // 3072

// Scratch (allocation-free rule: __device__ globals)
__device__ float g_qkv[(size_t)M_ROWS * QKV_N];   // [4096][3072]
__device__ float g_attn[(size_t)M_ROWS * C_DIM];  // [4096][1024]

// ---------------------------------------------------------------------------
// TF32 helpers
// ---------------------------------------------------------------------------
__device__ __forceinline__ uint32_t f2tf(float x) {
    uint32_t r;
    asm("cvt.rna.tf32.f32 %0, %1;" : "=r"(r) : "f"(x));
    return r;
}

// D += A(16x8,row) * B(8x8,col)  tf32 inputs, fp32 accum
__device__ __forceinline__ void mma8(float* c, const uint32_t* a, const uint32_t* b) {
    asm volatile(
        "mma.sync.aligned.m16n8k8.row.col.f32.tf32.tf32.f32 "
        "{%0,%1,%2,%3}, {%4,%5,%6,%7}, {%8,%9}, {%0,%1,%2,%3};"
        : "+f"(c[0]), "+f"(c[1]), "+f"(c[2]), "+f"(c[3])
        : "r"(a[0]), "r"(a[1]), "r"(a[2]), "r"(a[3]), "r"(b[0]), "r"(b[1]));
}

// ---------------------------------------------------------------------------
// TF32 GEMM NT: C[m][n] = sum_k A[m][k] * W[n][k] (+bias[n])
// 128x128x32 tile, 256 thr = 8 warps (4x2), warp tile 32x64.
// smem layout [k][m] / [k][n], stride 136 (136%32==8 -> frag loads conflict-free)
// ---------------------------------------------------------------------------
#define GLD 136

template<bool BIAS>
__global__ void __launch_bounds__(256) gemm_tf32(
    const float* __restrict__ A, const float* __restrict__ Wm,
    const float* __restrict__ bias, float* __restrict__ C,
    int M, int N, int K)
{
    __shared__ uint32_t As[32][GLD];
    __shared__ uint32_t Bs[32][GLD];

    const int tid  = threadIdx.x;
    const int lane = tid & 31, w = tid >> 5;
    const int qr = lane >> 2, ql = lane & 3;
    const int row0 = blockIdx.y * 128, col0 = blockIdx.x * 128;
    const int m0w = (w >> 1) * 32;      // warp m-origin (0,32,64,96)
    const int n0w = (w & 1) * 64;       // warp n-origin (0,64)

    // global load mapping: 2 threads per row, 16 k-floats each
    const int lr = tid >> 1;            // 0..127
    const int lk = (tid & 1) * 16;      // 0 or 16
    const float* Ap = A  + (size_t)(row0 + lr) * K + lk;
    const float* Wp = Wm + (size_t)(col0 + lr) * K + lk;

    float acc[16][4];
    #pragma unroll
    for (int i = 0; i < 16; i++) { acc[i][0] = acc[i][1] = acc[i][2] = acc[i][3] = 0.f; }

    for (int k0 = 0; k0 < K; k0 += 32) {
        float4 av[4], bv[4];
        #pragma unroll
        for (int i = 0; i < 4; i++) {
            av[i] = *(const float4*)(Ap + k0 + i * 4);
            bv[i] = *(const float4*)(Wp + k0 + i * 4);
        }
        __syncthreads();
        #pragma unroll
        for (int i = 0; i < 4; i++) {
            As[lk + i*4 + 0][lr] = f2tf(av[i].x);
            As[lk + i*4 + 1][lr] = f2tf(av[i].y);
            As[lk + i*4 + 2][lr] = f2tf(av[i].z);
            As[lk + i*4 + 3][lr] = f2tf(av[i].w);
            Bs[lk + i*4 + 0][lr] = f2tf(bv[i].x);
            Bs[lk + i*4 + 1][lr] = f2tf(bv[i].y);
            Bs[lk + i*4 + 2][lr] = f2tf(bv[i].z);
            Bs[lk + i*4 + 3][lr] = f2tf(bv[i].w);
        }
        __syncthreads();

        #pragma unroll
        for (int ks = 0; ks < 4; ks++) {
            const int kk = ks * 8;
            uint32_t a[2][4];
            #pragma unroll
            for (int mt = 0; mt < 2; mt++) {
                const int m = m0w + mt * 16;
                a[mt][0] = As[kk + ql    ][m + qr    ];
                a[mt][1] = As[kk + ql    ][m + qr + 8];
                a[mt][2] = As[kk + ql + 4][m + qr    ];
                a[mt][3] = As[kk + ql + 4][m + qr + 8];
            }
            #pragma unroll
            for (int nt = 0; nt < 8; nt++) {
                uint32_t b[2];
                b[0] = Bs[kk + ql    ][n0w + nt*8 + qr];
                b[1] = Bs[kk + ql + 4][n0w + nt*8 + qr];
                mma8(acc[0*8 + nt], a[0], b);
                mma8(acc[1*8 + nt], a[1], b);
            }
        }
    }

    // epilogue
    #pragma unroll
    for (int mt = 0; mt < 2; mt++) {
        #pragma unroll
        for (int nt = 0; nt < 8; nt++) {
            const float* c4 = acc[mt*8 + nt];
            const int col = col0 + n0w + nt*8 + 2*ql;
            float b0 = 0.f, b1 = 0.f;
            if (BIAS) { b0 = bias[col]; b1 = bias[col + 1]; }
            const int r0 = row0 + m0w + mt*16 + qr;
            *(float2*)(C + (size_t)r0 * N + col)       = make_float2(c4[0] + b0, c4[1] + b1);
            *(float2*)(C + (size_t)(r0 + 8) * N + col) = make_float2(c4[2] + b0, c4[3] + b1);
        }
    }
}

// ---------------------------------------------------------------------------
// Axial RoPE, in-place on q and k inside the qkv buffer.
// Torch .repeat tiling: element j in a 20-dim segment uses omega[j % 10],
// rotation partner is the adjacent element within the (2i, 2i+1) pair.
// ---------------------------------------------------------------------------
#define ROPE_TOTAL (2 * B_DIM * NH * N_DIM * 30)

__global__ void rope_kernel(float* __restrict__ qkv)
{
    int idx = blockIdx.x * blockDim.x + threadIdx.x;
    if (idx >= ROPE_TOTAL) return;
    int pair = idx % 30; int t = idx / 30;
    int n = t & 2047; t >>= 11;
    int h = t & 15;   t >>= 4;
    int b = t & 1;    int sel = t >> 1;   // 0 = q, 1 = k

    int seg = pair / 10;
    int ip  = pair - seg * 10;

    float p;
    if (seg == 0)      p = (float)(n >> 8);
    else if (seg == 1) p = (float)((n >> 4) & 15);
    else               p = (float)(n & 15);

    int j0 = 2 * ip, j1 = 2 * ip + 1;
    int f0 = (j0 < 10) ? j0 : j0 - 10;
    int f1 = (j1 < 10) ? j1 : j1 - 10;
    float om0 = __powf(10000.f, -0.1f * (float)f0);
    float om1 = __powf(10000.f, -0.1f * (float)f1);

    size_t base = ((size_t)(b * N_DIM + n)) * QKV_N + sel * C_DIM + h * HD + seg * 20;
    float x0 = qkv[base + j0];
    float x1 = qkv[base + j1];

    float sn0, cs0, sn1, cs1;
    sincosf(p * om0, &sn0, &cs0);
    sincosf(p * om1, &sn1, &cs1);

    qkv[base + j0] = x0 * cs0 - x1 * sn0;
    qkv[base + j1] = x1 * cs1 + x0 * sn1;
}

// ---------------------------------------------------------------------------
// Flash attention, TF32 tensor cores.
// CTA = 128 q-rows of one (b,h). 8 warps, warp owns m16 (rows w*16..w*16+15).
// K-tile = 64 cols. S = Q K^T and O += P V both via m16n8k8 tf32 mma.
// smem strides 68 (68%32==4 -> [m][k]-style frag loads conflict-free).
// ---------------------------------------------------------------------------
#define ALD 68
#define ATTN_SMEM ((128*ALD + 64*ALD + 64*ALD + 128*ALD) * 4)   // Qs,Ks,Vt,Ps

__global__ void __launch_bounds__(256) attn_tf32(
    const float* __restrict__ qkv, float* __restrict__ out)
{
    extern __shared__ uint32_t sm[];
    uint32_t* Qs = sm;                    // [128][68]  Q (tf32, pre-scaled)
    uint32_t* Ks = Qs + 128 * ALD;        // [64][68]   K natural [j][k]
    uint32_t* Vt = Ks + 64 * ALD;         // [64][68]   V transposed [c][j]
    uint32_t* Ps = Vt + 64 * ALD;         // [128][68]  P (tf32)

    const int tid  = threadIdx.x;
    const int lane = tid & 31, w = tid >> 5;
    const int qr = lane >> 2, ql = lane & 3;
    const int bh = blockIdx.y, b = bh >> 4, h = bh & 15;
    const int n0 = blockIdx.x * 128;
    const int m0 = w * 16;
    const float scale = 0.125f;           // hd^-0.5

    // Load Q tile [128][64], prescale + cvt to tf32
    {
        const int r  = tid >> 1;
        const int cb = (tid & 1) * 32;
        const float* src = qkv + ((size_t)(b * N_DIM + n0 + r)) * QKV_N + h * HD + cb;
        #pragma unroll
        for (int i = 0; i < 8; i++) {
            float4 v = *(const float4*)(src + i * 4);
            uint32_t* d = Qs + r * ALD + cb + i * 4;
            d[0] = f2tf(v.x * scale); d[1] = f2tf(v.y * scale);
            d[2] = f2tf(v.z * scale); d[3] = f2tf(v.w * scale);
        }
    }

    float m_lo = -1e30f, m_hi = -1e30f, l_lo = 0.f, l_hi = 0.f;
    float o[8][4];
    #pragma unroll
    for (int nt = 0; nt < 8; nt++) { o[nt][0] = o[nt][1] = o[nt][2] = o[nt][3] = 0.f; }

    for (int kt = 0; kt < N_DIM / 64; kt++) {
        __syncthreads();   // previous iteration's PV reads of Ks/Vt done
        // Load K (natural) and V (transposed) tiles, cvt to tf32
        {
            const int j  = tid >> 2;
            const int kb = (tid & 3) * 16;
            const float* ksrc = qkv + ((size_t)(b * N_DIM + kt * 64 + j)) * QKV_N + C_DIM + h * HD + kb;
            const float* vsrc = ksrc + C_DIM;
            #pragma unroll
            for (int i = 0; i < 4; i++) {
                float4 kv = *(const float4*)(ksrc + i * 4);
                uint32_t* d = Ks + j * ALD + kb + i * 4;
                d[0] = f2tf(kv.x); d[1] = f2tf(kv.y); d[2] = f2tf(kv.z); d[3] = f2tf(kv.w);
                float4 vv = *(const float4*)(vsrc + i * 4);
                const int c = kb + i * 4;
                Vt[(c + 0) * ALD + j] = f2tf(vv.x);
                Vt[(c + 1) * ALD + j] = f2tf(vv.y);
                Vt[(c + 2) * ALD + j] = f2tf(vv.z);
                Vt[(c + 3) * ALD + j] = f2tf(vv.w);
            }
        }
        __syncthreads();

        // S = Q K^T : warp m16 x 64 cols -> 8 n-tiles
        float S[8][4];
        #pragma unroll
        for (int nt = 0; nt < 8; nt++) { S[nt][0] = S[nt][1] = S[nt][2] = S[nt][3] = 0.f; }
        #pragma unroll
        for (int ks = 0; ks < 8; ks++) {
            const int kk = ks * 8;
            uint32_t a[4];
            a[0] = Qs[(m0 + qr    ) * ALD + kk + ql    ];
            a[1] = Qs[(m0 + qr + 8) * ALD + kk + ql    ];
            a[2] = Qs[(m0 + qr    ) * ALD + kk + ql + 4];
            a[3] = Qs[(m0 + qr + 8) * ALD + kk + ql + 4];
            #pragma unroll
            for (int nt = 0; nt < 8; nt++) {
                uint32_t bf[2];
                bf[0] = Ks[(nt*8 + qr) * ALD + kk + ql    ];
                bf[1] = Ks[(nt*8 + qr) * ALD + kk + ql + 4];
                mma8(S[nt], a, bf);
            }
        }

        // Online softmax. Lane owns rows (m0+qr) [c0,c1] and (m0+qr+8) [c2,c3];
        // full row lives in the 4 lanes of a quad -> shfl_xor 1,2.
        float mx0 = -1e30f, mx1 = -1e30f;
        #pragma unroll
        for (int nt = 0; nt < 8; nt++) {
            mx0 = fmaxf(mx0, fmaxf(S[nt][0], S[nt][1]));
            mx1 = fmaxf(mx1, fmaxf(S[nt][2], S[nt][3]));
        }
        mx0 = fmaxf(mx0, __shfl_xor_sync(0xffffffffu, mx0, 1));
        mx0 = fmaxf(mx0, __shfl_xor_sync(0xffffffffu, mx0, 2));
        mx1 = fmaxf(mx1, __shfl_xor_sync(0xffffffffu, mx1, 1));
        mx1 = fmaxf(mx1, __shfl_xor_sync(0xffffffffu, mx1, 2));

        const float mn0 = fmaxf(m_lo, mx0);
        const float mn1 = fmaxf(m_hi, mx1);
        const float al0 = __expf(m_lo - mn0);
        const float al1 = __expf(m_hi - mn1);
        m_lo = mn0; m_hi = mn1;

        float rs0 = 0.f, rs1 = 0.f;
        #pragma unroll
        for (int nt = 0; nt < 8; nt++) {
            S[nt][0] = __expf(S[nt][0] - mn0);
            S[nt][1] = __expf(S[nt][1] - mn0);
            S[nt][2] = __expf(S[nt][2] - mn1);
            S[nt][3] = __expf(S[nt][3] - mn1);
            rs0 += S[nt][0] + S[nt][1];
            rs1 += S[nt][2] + S[nt][3];
        }
        rs0 += __shfl_xor_sync(0xffffffffu, rs0, 1);
        rs0 += __shfl_xor_sync(0xffffffffu, rs0, 2);
        rs1 += __shfl_xor_sync(0xffffffffu, rs1, 1);
        rs1 += __shfl_xor_sync(0xffffffffu, rs1, 2);
        l_lo = l_lo * al0 + rs0;
        l_hi = l_hi * al1 + rs1;
        #pragma unroll
        for (int nt = 0; nt < 8; nt++) {
            o[nt][0] *= al0; o[nt][1] *= al0;
            o[nt][2] *= al1; o[nt][3] *= al1;
        }

        // P -> warp-private smem region (accum frag -> A frag layout bounce)
        #pragma unroll
        for (int nt = 0; nt < 8; nt++) {
            *(uint2*)(Ps + (m0 + qr    ) * ALD + nt*8 + 2*ql) =
                make_uint2(f2tf(S[nt][0]), f2tf(S[nt][1]));
            *(uint2*)(Ps + (m0 + qr + 8) * ALD + nt*8 + 2*ql) =
                make_uint2(f2tf(S[nt][2]), f2tf(S[nt][3]));
        }
        __syncwarp();

        // O += P V
        #pragma unroll
        for (int ks = 0; ks < 8; ks++) {
            const int kk = ks * 8;
            uint32_t a[4];
            a[0] = Ps[(m0 + qr    ) * ALD + kk + ql    ];
            a[1] = Ps[(m0 + qr + 8) * ALD + kk + ql    ];
            a[2] = Ps[(m0 + qr    ) * ALD + kk + ql + 4];
            a[3] = Ps[(m0 + qr + 8) * ALD + kk + ql + 4];
            #pragma unroll
            for (int nt = 0; nt < 8; nt++) {
                uint32_t bf[2];
                bf[0] = Vt[(nt*8 + qr) * ALD + kk + ql    ];
                bf[1] = Vt[(nt*8 + qr) * ALD + kk + ql + 4];
                mma8(o[nt], a, bf);
            }
        }
        __syncwarp();   // PV reads of Ps done before next iteration overwrites
    }

    // Normalize + write out[b][n][h*64 + c]
    const float i0 = 1.f / l_lo, i1 = 1.f / l_hi;
    #pragma unroll
    for (int nt = 0; nt < 8; nt++) {
        const size_t r0 = ((size_t)(b * N_DIM + n0 + m0 + qr)) * C_DIM + h * HD + nt*8 + 2*ql;
        *(float2*)(out + r0)             = make_float2(o[nt][0] * i0, o[nt][1] * i0);
        *(float2*)(out + r0 + 8 * C_DIM) = make_float2(o[nt][2] * i1, o[nt][3] * i1);
    }
}

// ---------------------------------------------------------------------------
extern "C" void kernel_launch(void* const* d_in, const int* in_sizes, int n_in,
                              void* d_out, int out_size)
{
    const float* x     = (const float*)d_in[0];
    const float* Wqkv  = (const float*)d_in[1];
    const float* Wproj = (const float*)d_in[2];
    const float* bproj = (const float*)d_in[3];
    float* out = (float*)d_out;

    float *qkv_ptr, *attn_ptr;
    cudaGetSymbolAddress((void**)&qkv_ptr,  g_qkv);
    cudaGetSymbolAddress((void**)&attn_ptr, g_attn);

    cudaFuncSetAttribute(attn_tf32,
                         cudaFuncAttributeMaxDynamicSharedMemorySize, ATTN_SMEM);

    // 1) fused QKV projection: [4096,1024] x [3072,1024]^T -> [4096,3072]
    gemm_tf32<false><<<dim3(QKV_N/128, M_ROWS/128), 256>>>(
        x, Wqkv, nullptr, qkv_ptr, M_ROWS, QKV_N, C_DIM);

    // 2) axial RoPE on q,k (in place)
    rope_kernel<<<(ROPE_TOTAL + 255) / 256, 256>>>(qkv_ptr);

    // 3) SDPA -> [4096,1024] (already in (b,n,h*hd) layout)
    attn_tf32<<<dim3(N_DIM/128, B_DIM*NH), 256, ATTN_SMEM>>>(qkv_ptr, attn_ptr);

    // 4) output projection + bias
    gemm_tf32<true><<<dim3(C_DIM/128, M_ROWS/128), 256>>>(
        attn_ptr, Wproj, bproj, out, M_ROWS, C_DIM, C_DIM);
}

// round 17
// speedup vs baseline: 2.9824x; 1.1853x over previous
#include <cuda_runtime.h>
#include <math.h>
#include <stdint.h>

#define B_DIM   2
#define N_DIM   2048
#define C_DIM   1024
#define NH      16
#define HD      64
#define M_ROWS  (B_DIM * N_DIM)          // 4096
#define QKV_N   (3 * C_DIM)              // 3072

// Scratch (allocation-free rule: __device__ globals)
__device__ float g_qkv[(size_t)M_ROWS * QKV_N];   // [4096][3072]
__device__ float g_attn[(size_t)M_ROWS * C_DIM];  // [4096][1024]

// ---------------------------------------------------------------------------
// TF32 / ldmatrix helpers
// ---------------------------------------------------------------------------
__device__ __forceinline__ uint32_t f2tf(float x) {
    uint32_t r;
    asm("cvt.rna.tf32.f32 %0, %1;" : "=r"(r) : "f"(x));
    return r;
}

// D += A(16x8,row) * B(8x8,col)  tf32 inputs, fp32 accum
__device__ __forceinline__ void mma8(float* c, const uint32_t* a, const uint32_t* b) {
    asm volatile(
        "mma.sync.aligned.m16n8k8.row.col.f32.tf32.tf32.f32 "
        "{%0,%1,%2,%3}, {%4,%5,%6,%7}, {%8,%9}, {%0,%1,%2,%3};"
        : "+f"(c[0]), "+f"(c[1]), "+f"(c[2]), "+f"(c[3])
        : "r"(a[0]), "r"(a[1]), "r"(a[2]), "r"(a[3]), "r"(b[0]), "r"(b[1]));
}

__device__ __forceinline__ void ldsm4(uint32_t* r, uint32_t addr) {
    asm volatile("ldmatrix.sync.aligned.m8n8.x4.shared.b16 {%0,%1,%2,%3}, [%4];"
        : "=r"(r[0]), "=r"(r[1]), "=r"(r[2]), "=r"(r[3]) : "r"(addr));
}

__device__ __forceinline__ uint32_t sptr(const void* p) {
    return (uint32_t)__cvta_generic_to_shared(p);
}

// ---------------------------------------------------------------------------
// TF32 GEMM NT: C[m][n] = sum_k A[m][k] * W[n][k] (+bias[n])
// 128x128x32 tile, 256 thr = 8 warps (4x2), warp tile 32x64.
// smem [row][k] pitch 36 words (36%32==4 -> ldmatrix conflict-free).
// Register double-buffered global loads; ldmatrix.x4 frag loads.
// ---------------------------------------------------------------------------
#define GLDK 36

template<bool BIAS>
__global__ void __launch_bounds__(256, 2) gemm_tf32(
    const float* __restrict__ A, const float* __restrict__ Wm,
    const float* __restrict__ bias, float* __restrict__ C,
    int M, int N, int K)
{
    __shared__ uint32_t As[128][GLDK];
    __shared__ uint32_t Bs[128][GLDK];

    const int tid  = threadIdx.x;
    const int lane = tid & 31, w = tid >> 5;
    const int qr = lane >> 2, ql = lane & 3;
    const int row0 = blockIdx.y * 128, col0 = blockIdx.x * 128;
    const int m0w = (w >> 1) * 32;      // warp m-origin (0,32,64,96)
    const int n0w = (w & 1) * 64;       // warp n-origin (0,64)

    // global load mapping: 2 threads per row, 16 k-floats each
    const int lr = tid >> 1;            // 0..127
    const int lk = (tid & 1) * 16;      // 0 or 16
    const float* Ap = A  + (size_t)(row0 + lr) * K + lk;
    const float* Wp = Wm + (size_t)(col0 + lr) * K + lk;

    // ldmatrix per-lane addresses
    const int arow = (lane & 7) + ((lane >> 3) & 1) * 8;   // A x4 row pattern
    const int akh  = (lane >> 4) * 4;                      // A k-half
    const uint32_t aAddr0 = sptr(&As[m0w + arow][akh]);
    const uint32_t aAddr1 = sptr(&As[m0w + 16 + arow][akh]);
    const int brow = (lane & 7) + ((lane >> 4) & 1) * 8;   // B x4 row pattern
    const int bkh  = ((lane >> 3) & 1) * 4;                // B k-half
    uint32_t bAddr[4];
    #pragma unroll
    for (int nt2 = 0; nt2 < 4; nt2++)
        bAddr[nt2] = sptr(&Bs[n0w + nt2 * 16 + brow][bkh]);

    float4 av[4], bv[4];
    #pragma unroll
    for (int i = 0; i < 4; i++) {
        av[i] = *(const float4*)(Ap + i * 4);
        bv[i] = *(const float4*)(Wp + i * 4);
    }

    float acc[16][4];
    #pragma unroll
    for (int i = 0; i < 16; i++) { acc[i][0] = acc[i][1] = acc[i][2] = acc[i][3] = 0.f; }

    const int nIter = K >> 5;
    for (int it = 0; it < nIter; ++it) {
        __syncthreads();
        #pragma unroll
        for (int i = 0; i < 4; i++) {
            uint4 ua = make_uint4(f2tf(av[i].x), f2tf(av[i].y), f2tf(av[i].z), f2tf(av[i].w));
            *(uint4*)&As[lr][lk + i * 4] = ua;
            uint4 ub = make_uint4(f2tf(bv[i].x), f2tf(bv[i].y), f2tf(bv[i].z), f2tf(bv[i].w));
            *(uint4*)&Bs[lr][lk + i * 4] = ub;
        }
        __syncthreads();
        if (it + 1 < nIter) {
            const float* Ap2 = Ap + (it + 1) * 32;
            const float* Wp2 = Wp + (it + 1) * 32;
            #pragma unroll
            for (int i = 0; i < 4; i++) {
                av[i] = *(const float4*)(Ap2 + i * 4);
                bv[i] = *(const float4*)(Wp2 + i * 4);
            }
        }
        #pragma unroll
        for (int ks = 0; ks < 4; ks++) {
            const uint32_t koff = ks * 8 * 4;   // bytes
            uint32_t a0[4], a1[4];
            ldsm4(a0, aAddr0 + koff);
            ldsm4(a1, aAddr1 + koff);
            #pragma unroll
            for (int nt2 = 0; nt2 < 4; nt2++) {
                uint32_t bb[4];
                ldsm4(bb, bAddr[nt2] + koff);
                mma8(acc[nt2 * 2],         a0, bb);
                mma8(acc[nt2 * 2 + 1],     a0, bb + 2);
                mma8(acc[8 + nt2 * 2],     a1, bb);
                mma8(acc[8 + nt2 * 2 + 1], a1, bb + 2);
            }
        }
    }

    // epilogue
    #pragma unroll
    for (int mt = 0; mt < 2; mt++) {
        #pragma unroll
        for (int nt = 0; nt < 8; nt++) {
            const float* c4 = acc[mt * 8 + nt];
            const int col = col0 + n0w + nt * 8 + 2 * ql;
            float b0 = 0.f, b1 = 0.f;
            if (BIAS) { b0 = bias[col]; b1 = bias[col + 1]; }
            const int r0 = row0 + m0w + mt * 16 + qr;
            *(float2*)(C + (size_t)r0 * N + col)       = make_float2(c4[0] + b0, c4[1] + b1);
            *(float2*)(C + (size_t)(r0 + 8) * N + col) = make_float2(c4[2] + b0, c4[3] + b1);
        }
    }
}

// ---------------------------------------------------------------------------
// Axial RoPE, in-place on q and k inside the qkv buffer (unchanged).
// ---------------------------------------------------------------------------
#define ROPE_TOTAL (2 * B_DIM * NH * N_DIM * 30)

__global__ void rope_kernel(float* __restrict__ qkv)
{
    int idx = blockIdx.x * blockDim.x + threadIdx.x;
    if (idx >= ROPE_TOTAL) return;
    int pair = idx % 30; int t = idx / 30;
    int n = t & 2047; t >>= 11;
    int h = t & 15;   t >>= 4;
    int b = t & 1;    int sel = t >> 1;   // 0 = q, 1 = k

    int seg = pair / 10;
    int ip  = pair - seg * 10;

    float p;
    if (seg == 0)      p = (float)(n >> 8);
    else if (seg == 1) p = (float)((n >> 4) & 15);
    else               p = (float)(n & 15);

    int j0 = 2 * ip, j1 = 2 * ip + 1;
    int f0 = (j0 < 10) ? j0 : j0 - 10;
    int f1 = (j1 < 10) ? j1 : j1 - 10;
    float om0 = __powf(10000.f, -0.1f * (float)f0);
    float om1 = __powf(10000.f, -0.1f * (float)f1);

    size_t base = ((size_t)(b * N_DIM + n)) * QKV_N + sel * C_DIM + h * HD + seg * 20;
    float x0 = qkv[base + j0];
    float x1 = qkv[base + j1];

    float sn0, cs0, sn1, cs1;
    sincosf(p * om0, &sn0, &cs0);
    sincosf(p * om1, &sn1, &cs1);

    qkv[base + j0] = x0 * cs0 - x1 * sn0;
    qkv[base + j1] = x1 * cs1 + x0 * sn1;
}

// ---------------------------------------------------------------------------
// Flash attention, TF32 tensor cores + ldmatrix + prefetched K/V.
// CTA = 128 q-rows of one (b,h). 8 warps, warp owns m16.
// K-tile = 64. smem pitch 68 words (68%32==4 -> ldmatrix conflict-free).
// ---------------------------------------------------------------------------
#define ALD 68
#define ATTN_SMEM ((128*ALD + 64*ALD + 64*ALD + 128*ALD) * 4)   // Qs,Ks,Vt,Ps

__global__ void __launch_bounds__(256, 2) attn_tf32(
    const float* __restrict__ qkv, float* __restrict__ out)
{
    extern __shared__ uint32_t sm[];
    uint32_t* Qs = sm;                    // [128][68]  Q (tf32, pre-scaled)
    uint32_t* Ks = Qs + 128 * ALD;        // [64][68]   K natural [j][k]
    uint32_t* Vt = Ks + 64 * ALD;         // [64][68]   V transposed [c][j]
    uint32_t* Ps = Vt + 64 * ALD;         // [128][68]  P (tf32)

    const int tid  = threadIdx.x;
    const int lane = tid & 31, w = tid >> 5;
    const int qr = lane >> 2, ql = lane & 3;
    const int bh = blockIdx.y, b = bh >> 4, h = bh & 15;
    const int n0 = blockIdx.x * 128;
    const int m0 = w * 16;
    const float scale = 0.125f;           // hd^-0.5

    // ldmatrix per-lane addresses
    const int arow = (lane & 7) + ((lane >> 3) & 1) * 8;
    const int akh  = (lane >> 4) * 4;
    const uint32_t qAddr = sptr(Qs + (m0 + arow) * ALD + akh);
    const uint32_t pAddr = sptr(Ps + (m0 + arow) * ALD + akh);
    const int brow = (lane & 7) + ((lane >> 4) & 1) * 8;
    const int bkh  = ((lane >> 3) & 1) * 4;
    uint32_t kAddr[4], vAddr[4];
    #pragma unroll
    for (int nt2 = 0; nt2 < 4; nt2++) {
        kAddr[nt2] = sptr(Ks + (nt2 * 16 + brow) * ALD + bkh);
        vAddr[nt2] = sptr(Vt + (nt2 * 16 + brow) * ALD + bkh);
    }

    // Load Q tile [128][64], prescale + cvt to tf32
    {
        const int r  = tid >> 1;
        const int cb = (tid & 1) * 32;
        const float* src = qkv + ((size_t)(b * N_DIM + n0 + r)) * QKV_N + h * HD + cb;
        #pragma unroll
        for (int i = 0; i < 8; i++) {
            float4 v = *(const float4*)(src + i * 4);
            uint4 u = make_uint4(f2tf(v.x * scale), f2tf(v.y * scale),
                                 f2tf(v.z * scale), f2tf(v.w * scale));
            *(uint4*)(Qs + r * ALD + cb + i * 4) = u;
        }
    }

    // staging mapping: thread -> K row j (16 cols at kb), V row j (cols 8u+2t+{0,1})
    const int j  = tid >> 2;
    const int t4 = tid & 3;
    const int kb = t4 * 16;
    const float* kRow0 = qkv + ((size_t)(b * N_DIM + j)) * QKV_N + C_DIM + h * HD;

    float4 kst[4];
    float2 vst[8];
    {
        const float* kr = kRow0;                  // kt = 0
        #pragma unroll
        for (int i = 0; i < 4; i++) kst[i] = *(const float4*)(kr + kb + i * 4);
        #pragma unroll
        for (int u = 0; u < 8; u++) vst[u] = *(const float2*)(kr + C_DIM + 8 * u + 2 * t4);
    }

    float m_lo = -1e30f, m_hi = -1e30f, l_lo = 0.f, l_hi = 0.f;
    float o[8][4];
    #pragma unroll
    for (int nt = 0; nt < 8; nt++) { o[nt][0] = o[nt][1] = o[nt][2] = o[nt][3] = 0.f; }

    for (int kt = 0; kt < N_DIM / 64; kt++) {
        __syncthreads();   // previous iteration's PV reads of Ks/Vt done
        // STS K (natural rows) and V (transposed, conflict-free mapping)
        #pragma unroll
        for (int i = 0; i < 4; i++) {
            uint4 u = make_uint4(f2tf(kst[i].x), f2tf(kst[i].y), f2tf(kst[i].z), f2tf(kst[i].w));
            *(uint4*)(Ks + j * ALD + kb + i * 4) = u;
        }
        #pragma unroll
        for (int u = 0; u < 8; u++) {
            const int c0 = 8 * u + 2 * t4;
            Vt[(c0    ) * ALD + j] = f2tf(vst[u].x);
            Vt[(c0 + 1) * ALD + j] = f2tf(vst[u].y);
        }
        __syncthreads();
        if (kt + 1 < N_DIM / 64) {   // prefetch next tile into regs
            const float* kr = kRow0 + (size_t)(kt + 1) * 64 * QKV_N;
            #pragma unroll
            for (int i = 0; i < 4; i++) kst[i] = *(const float4*)(kr + kb + i * 4);
            #pragma unroll
            for (int u = 0; u < 8; u++) vst[u] = *(const float2*)(kr + C_DIM + 8 * u + 2 * t4);
        }

        // S = Q K^T
        float S[8][4];
        #pragma unroll
        for (int nt = 0; nt < 8; nt++) { S[nt][0] = S[nt][1] = S[nt][2] = S[nt][3] = 0.f; }
        #pragma unroll
        for (int ks = 0; ks < 8; ks++) {
            const uint32_t koff = ks * 8 * 4;
            uint32_t a[4];
            ldsm4(a, qAddr + koff);
            #pragma unroll
            for (int nt2 = 0; nt2 < 4; nt2++) {
                uint32_t bb[4];
                ldsm4(bb, kAddr[nt2] + koff);
                mma8(S[nt2 * 2],     a, bb);
                mma8(S[nt2 * 2 + 1], a, bb + 2);
            }
        }

        // Online softmax (row split across quad lanes -> shfl_xor 1,2)
        float mx0 = -1e30f, mx1 = -1e30f;
        #pragma unroll
        for (int nt = 0; nt < 8; nt++) {
            mx0 = fmaxf(mx0, fmaxf(S[nt][0], S[nt][1]));
            mx1 = fmaxf(mx1, fmaxf(S[nt][2], S[nt][3]));
        }
        mx0 = fmaxf(mx0, __shfl_xor_sync(0xffffffffu, mx0, 1));
        mx0 = fmaxf(mx0, __shfl_xor_sync(0xffffffffu, mx0, 2));
        mx1 = fmaxf(mx1, __shfl_xor_sync(0xffffffffu, mx1, 1));
        mx1 = fmaxf(mx1, __shfl_xor_sync(0xffffffffu, mx1, 2));

        const float mn0 = fmaxf(m_lo, mx0);
        const float mn1 = fmaxf(m_hi, mx1);
        const float al0 = __expf(m_lo - mn0);
        const float al1 = __expf(m_hi - mn1);
        m_lo = mn0; m_hi = mn1;

        float rs0 = 0.f, rs1 = 0.f;
        #pragma unroll
        for (int nt = 0; nt < 8; nt++) {
            S[nt][0] = __expf(S[nt][0] - mn0);
            S[nt][1] = __expf(S[nt][1] - mn0);
            S[nt][2] = __expf(S[nt][2] - mn1);
            S[nt][3] = __expf(S[nt][3] - mn1);
            rs0 += S[nt][0] + S[nt][1];
            rs1 += S[nt][2] + S[nt][3];
        }
        rs0 += __shfl_xor_sync(0xffffffffu, rs0, 1);
        rs0 += __shfl_xor_sync(0xffffffffu, rs0, 2);
        rs1 += __shfl_xor_sync(0xffffffffu, rs1, 1);
        rs1 += __shfl_xor_sync(0xffffffffu, rs1, 2);
        l_lo = l_lo * al0 + rs0;
        l_hi = l_hi * al1 + rs1;
        #pragma unroll
        for (int nt = 0; nt < 8; nt++) {
            o[nt][0] *= al0; o[nt][1] *= al0;
            o[nt][2] *= al1; o[nt][3] *= al1;
        }

        // P -> warp-private smem region
        #pragma unroll
        for (int nt = 0; nt < 8; nt++) {
            *(uint2*)(Ps + (m0 + qr    ) * ALD + nt * 8 + 2 * ql) =
                make_uint2(f2tf(S[nt][0]), f2tf(S[nt][1]));
            *(uint2*)(Ps + (m0 + qr + 8) * ALD + nt * 8 + 2 * ql) =
                make_uint2(f2tf(S[nt][2]), f2tf(S[nt][3]));
        }
        __syncwarp();

        // O += P V
        #pragma unroll
        for (int ks = 0; ks < 8; ks++) {
            const uint32_t koff = ks * 8 * 4;
            uint32_t a[4];
            ldsm4(a, pAddr + koff);
            #pragma unroll
            for (int nt2 = 0; nt2 < 4; nt2++) {
                uint32_t bb[4];
                ldsm4(bb, vAddr[nt2] + koff);
                mma8(o[nt2 * 2],     a, bb);
                mma8(o[nt2 * 2 + 1], a, bb + 2);
            }
        }
        __syncwarp();   // PV reads of Ps done before next iteration overwrites
    }

    // Normalize + write out[b][n][h*64 + c]
    const float i0 = 1.f / l_lo, i1 = 1.f / l_hi;
    #pragma unroll
    for (int nt = 0; nt < 8; nt++) {
        const size_t r0 = ((size_t)(b * N_DIM + n0 + m0 + qr)) * C_DIM + h * HD + nt * 8 + 2 * ql;
        *(float2*)(out + r0)             = make_float2(o[nt][0] * i0, o[nt][1] * i0);
        *(float2*)(out + r0 + 8 * C_DIM) = make_float2(o[nt][2] * i1, o[nt][3] * i1);
    }
}

// ---------------------------------------------------------------------------
extern "C" void kernel_launch(void* const* d_in, const int* in_sizes, int n_in,
                              void* d_out, int out_size)
{
    const float* x     = (const float*)d_in[0];
    const float* Wqkv  = (const float*)d_in[1];
    const float* Wproj = (const float*)d_in[2];
    const float* bproj = (const float*)d_in[3];
    float* out = (float*)d_out;

    float *qkv_ptr, *attn_ptr;
    cudaGetSymbolAddress((void**)&qkv_ptr,  g_qkv);
    cudaGetSymbolAddress((void**)&attn_ptr, g_attn);

    cudaFuncSetAttribute(attn_tf32,
                         cudaFuncAttributeMaxDynamicSharedMemorySize, ATTN_SMEM);

    // 1) fused QKV projection: [4096,1024] x [3072,1024]^T -> [4096,3072]
    gemm_tf32<false><<<dim3(QKV_N/128, M_ROWS/128), 256>>>(
        x, Wqkv, nullptr, qkv_ptr, M_ROWS, QKV_N, C_DIM);

    // 2) axial RoPE on q,k (in place)
    rope_kernel<<<(ROPE_TOTAL + 255) / 256, 256>>>(qkv_ptr);

    // 3) SDPA -> [4096,1024] (already in (b,n,h*hd) layout)
    attn_tf32<<<dim3(N_DIM/128, B_DIM*NH), 256, ATTN_SMEM>>>(qkv_ptr, attn_ptr);

    // 4) output projection + bias
    gemm_tf32<true><<<dim3(C_DIM/128, M_ROWS/128), 256>>>(
        attn_ptr, Wproj, bproj, out, M_ROWS, C_DIM, C_DIM);
}